// round 2
// baseline (speedup 1.0000x reference)
#include <cuda_runtime.h>
#include <cuda_bf16.h>

// Problem dims (fixed by the dataset)
#define B  512
#define T  1024
#define IN 128
#define H  256

// ---------------- scratch (device globals: no allocation allowed) -------------
__device__ float g_cur1[(size_t)B * T * H];   // [B][T][H]  512 MB
__device__ float g_w1t[IN * H];               // [i][h]
__device__ float g_w2t[H * H];                // [j][h]  (W2 transposed)

// packed fp32x2 helpers (sm_103a FFMA2 — only reachable via PTX)
#define FMA2(acc, a, b) \
    asm("fma.rn.f32x2 %0, %1, %2, %0;" : "+l"(acc) : "l"(a), "l"(b))
#define ADD2(d, a, b) \
    asm("add.rn.f32x2 %0, %1, %2;" : "=l"(d) : "l"(a), "l"(b))
#define PACK2(d, f) \
    asm("mov.b64 %0, {%1, %1};" : "=l"(d) : "r"(__float_as_uint(f)))

// ---------------- prep: transpose W1 and W2 ----------------------------------
__global__ void prep_kernel(const float* __restrict__ W1, const float* __restrict__ W2) {
    int tid = blockIdx.x * blockDim.x + threadIdx.x;   // 0 .. 65535
    if (tid < H * IN) {
        int h = tid / IN, i = tid % IN;                // W1 [H][IN]
        g_w1t[i * H + h] = W1[tid];
    }
    if (tid < H * H) {
        int h = tid >> 8, j = tid & 255;               // W2 [H][H]
        g_w2t[j * H + h] = W2[tid];
    }
}

// ---------------- phase 1: cur1 = x @ W1^T + b1 -------------------------------
// C[bt][h], M = B*T = 524288, N = 256, K = 128.
// 64x128 tile, BK=16, 256 threads, 4x8 micro-tile, packed f32x2 FMAs.
#define BM 64
#define BN 128
#define BK 16

__global__ void __launch_bounds__(256) gemm_cur1(const float* __restrict__ x,
                                                 const float* __restrict__ b1) {
    __shared__ float xs[BM][BK];
    __shared__ float ws[BK][BN];

    const int bm = blockIdx.x * BM;       // bt offset
    const int bn = blockIdx.y * BN;       // h offset
    const int tid = threadIdx.x;
    const int tx = tid & 15;              // 0..15  (col group: 8 cols = 4 f32x2)
    const int ty = tid >> 4;              // 0..15  (row group: 4 rows)

    unsigned long long acc[4][4];
    #pragma unroll
    for (int r = 0; r < 4; r++)
        #pragma unroll
        for (int p = 0; p < 4; p++) acc[r][p] = 0ull;

    for (int k0 = 0; k0 < IN; k0 += BK) {
        // load xs: 64 x 16 floats = 256 float4, 1 per thread
        {
            int r = tid >> 2, c4 = tid & 3;
            *(float4*)&xs[r][c4 * 4] =
                *(const float4*)&x[(size_t)(bm + r) * IN + k0 + c4 * 4];
        }
        // load ws (from w1t [IN][H]): 16 x 128 floats = 512 float4, 2 per thread
        #pragma unroll
        for (int l = 0; l < 2; l++) {
            int idx = tid + l * 256;
            int r = idx >> 5, c4 = idx & 31;
            *(float4*)&ws[r][c4 * 4] =
                *(const float4*)&g_w1t[(size_t)(k0 + r) * H + bn + c4 * 4];
        }
        __syncthreads();

        #pragma unroll
        for (int k = 0; k < BK; k++) {
            ulonglong2 bq0 = *(ulonglong2*)&ws[k][tx * 8];      // cols 0..3
            ulonglong2 bq1 = *(ulonglong2*)&ws[k][tx * 8 + 4];  // cols 4..7
            #pragma unroll
            for (int r = 0; r < 4; r++) {
                unsigned long long ad;
                PACK2(ad, xs[ty * 4 + r][k]);
                FMA2(acc[r][0], ad, bq0.x);
                FMA2(acc[r][1], ad, bq0.y);
                FMA2(acc[r][2], ad, bq1.x);
                FMA2(acc[r][3], ad, bq1.y);
            }
        }
        __syncthreads();
    }

    // bias (packed) + store
    ulonglong2 bias0 = *(const ulonglong2*)&b1[bn + tx * 8];
    ulonglong2 bias1 = *(const ulonglong2*)&b1[bn + tx * 8 + 4];
    #pragma unroll
    for (int r = 0; r < 4; r++) {
        ulonglong2 o0, o1;
        ADD2(o0.x, acc[r][0], bias0.x);
        ADD2(o0.y, acc[r][1], bias0.y);
        ADD2(o1.x, acc[r][2], bias1.x);
        ADD2(o1.y, acc[r][3], bias1.y);
        float* dst = &g_cur1[(size_t)(bm + ty * 4 + r) * H + bn + tx * 8];
        *(ulonglong2*)dst       = o0;
        *(ulonglong2*)(dst + 4) = o1;
    }
}

// ---------------- phase 2: sequential scan, one CTA per batch element ---------
// 256 threads; thread t owns neuron h=t for membrane state.
// Gather is cooperative + vectorized: 4 row-slices x 64 float4 chunks,
// partials combined through a 4KB smem stage.
__global__ void __launch_bounds__(256) scan_kernel(const float* __restrict__ b2,
                                                   const float* __restrict__ wout,
                                                   const float* __restrict__ boutp,
                                                   const float* __restrict__ pb1,
                                                   const float* __restrict__ pb2,
                                                   const float* __restrict__ pbo,
                                                   float* __restrict__ out) {
    const int b    = blockIdx.x;
    const int tid  = threadIdx.x;
    const int lane = tid & 31;
    const int wid  = tid >> 5;
    const int g    = tid >> 6;   // row-slice 0..3
    const int c    = tid & 63;   // float4 chunk 0..63

    const float bt1 = fminf(fmaxf(pb1[0], 0.f), 1.f);
    const float bt2 = fminf(fmaxf(pb2[0], 0.f), 1.f);
    const float bto = fminf(fmaxf(pbo[0], 0.f), 1.f);
    const float boutv = boutp[0];
    const float b2v   = b2[tid];
    const float woutv = wout[tid];

    __shared__ unsigned       bits[8];
    __shared__ unsigned short list[H];
    __shared__ float          part[4][H];   // [slice][neuron]
    __shared__ float          wsum[8];

    float mem1 = 0.f, mem2 = 0.f, memo = 0.f;
    float s1p = 0.f, s2p = 0.f;

    const float* c1p  = g_cur1 + (size_t)b * T * H + tid;
    float*       outp = out + (size_t)b * T;

    // software-pipeline cur1 one step ahead (hide DRAM latency of the stream)
    float c1 = c1p[0];

    for (int t = 0; t < T; t++) {
        float c1n = (t + 1 < T) ? c1p[(size_t)(t + 1) * H] : 0.f;

        // layer 1 membrane update (reset uses previous-step spike)
        mem1 = bt1 * mem1 + c1 - s1p;
        bool s1 = mem1 > 1.0f;

        unsigned bal = __ballot_sync(0xffffffffu, s1);
        if (lane == 0) bits[wid] = bal;
        __syncthreads();                              // sync1: bits ready

        // build compact active list (uniform across threads)
        int n = 0, myoff = 0;
        #pragma unroll
        for (int w = 0; w < 8; w++) {
            int cnt = __popc(bits[w]);
            if (w < wid) myoff += cnt;
            n += cnt;
        }
        if (s1) {
            int pos = myoff + __popc(bal & ((1u << lane) - 1u));
            list[pos] = (unsigned short)tid;
        }
        s1p = s1 ? 1.f : 0.f;
        __syncthreads();                              // sync2: list ready

        // cooperative float4 gather: slice g handles rows k = g, g+4, ...
        float4 aA = make_float4(0.f, 0.f, 0.f, 0.f);
        float4 aB = make_float4(0.f, 0.f, 0.f, 0.f);
        int k = g;
        for (; k + 4 < n; k += 8) {
            int j0 = list[k];
            int j1 = list[k + 4];
            float4 w0 = *(const float4*)&g_w2t[j0 * H + c * 4];
            float4 w1 = *(const float4*)&g_w2t[j1 * H + c * 4];
            aA.x += w0.x; aA.y += w0.y; aA.z += w0.z; aA.w += w0.w;
            aB.x += w1.x; aB.y += w1.y; aB.z += w1.z; aB.w += w1.w;
        }
        if (k < n) {
            int j0 = list[k];
            float4 w0 = *(const float4*)&g_w2t[j0 * H + c * 4];
            aA.x += w0.x; aA.y += w0.y; aA.z += w0.z; aA.w += w0.w;
        }
        aA.x += aB.x; aA.y += aB.y; aA.z += aB.z; aA.w += aB.w;
        *(float4*)&part[g][c * 4] = aA;
        __syncthreads();                              // sync3: partials ready

        float cur2 = b2v + ((part[0][tid] + part[1][tid]) +
                            (part[2][tid] + part[3][tid]));

        // layer 2 membrane update
        mem2 = bt2 * mem2 + cur2 - s2p;
        bool s2 = mem2 > 1.0f;
        s2p = s2 ? 1.f : 0.f;

        // readout: out = spk2 @ Wout^T + bout ; mem_out leaky-integrates
        float v = s2 ? woutv : 0.f;
        #pragma unroll
        for (int off = 16; off; off >>= 1) v += __shfl_xor_sync(0xffffffffu, v, off);
        if (lane == 0) wsum[wid] = v;
        __syncthreads();                              // sync4: wsum ready

        if (tid == 0) {
            float o = boutv;
            #pragma unroll
            for (int w = 0; w < 8; w++) o += wsum[w];
            memo = bto * memo + o;
            outp[t] = memo;
        }

        c1 = c1n;
    }
}

// ---------------- launcher ----------------------------------------------------
extern "C" void kernel_launch(void* const* d_in, const int* in_sizes, int n_in,
                              void* d_out, int out_size) {
    const float* x     = (const float*)d_in[0];   // [B,T,IN]
    const float* W1    = (const float*)d_in[1];   // [H,IN]
    const float* b1    = (const float*)d_in[2];   // [H]
    const float* W2    = (const float*)d_in[3];   // [H,H]
    const float* b2    = (const float*)d_in[4];   // [H]
    const float* Wout  = (const float*)d_in[5];   // [1,H]
    const float* bout  = (const float*)d_in[6];   // [1]
    const float* beta1 = (const float*)d_in[7];
    const float* beta2 = (const float*)d_in[8];
    const float* betao = (const float*)d_in[9];
    float* out = (float*)d_out;                   // [B,T,1]

    prep_kernel<<<(H * H + 255) / 256, 256>>>(W1, W2);

    dim3 ggrid(B * T / BM, H / BN);
    gemm_cur1<<<ggrid, 256>>>(x, b1);

    scan_kernel<<<B, 256>>>(b2, Wout, bout, beta1, beta2, betao, out);
}

// round 3
// speedup vs baseline: 1.0739x; 1.0739x over previous
#include <cuda_runtime.h>
#include <cuda_bf16.h>

// Problem dims (fixed by the dataset)
#define B  512
#define T  1024
#define IN 128
#define H  256

// ---------------- scratch (device globals: no allocation allowed) -------------
__device__ float    g_cur1[(size_t)B * T * H];   // [B][T][H]  512 MB
__device__ float    g_w1t[IN * H];               // [k][h]
__device__ float    g_w2t[H * H];                // [j][h]  (W2 transposed)
__device__ unsigned g_spk[(size_t)B * T * 8];    // spk2 ballots, 16 MB

// packed fp32x2 helpers (sm_103a FFMA2 — only reachable via PTX)
#define FMA2(acc, a, b) \
    asm("fma.rn.f32x2 %0, %1, %2, %0;" : "+l"(acc) : "l"(a), "l"(b))
#define ADD2(d, a, b) \
    asm("add.rn.f32x2 %0, %1, %2;" : "=l"(d) : "l"(a), "l"(b))
#define PACK2(d, f) \
    asm("mov.b64 %0, {%1, %1};" : "=l"(d) : "r"(__float_as_uint(f)))

// ---------------- prep: transpose W1 and W2 ----------------------------------
__global__ void prep_kernel(const float* __restrict__ W1, const float* __restrict__ W2) {
    int tid = blockIdx.x * blockDim.x + threadIdx.x;   // 0 .. 65535
    if (tid < H * IN) {
        int h = tid / IN, i = tid % IN;                // W1 [H][IN]
        g_w1t[i * H + h] = W1[tid];
    }
    if (tid < H * H) {
        int h = tid >> 8, j = tid & 255;               // W2 [H][H]
        g_w2t[j * H + h] = W2[tid];
    }
}

// ---------------- phase 1: cur1 = x @ W1^T + b1 -------------------------------
// C[bt][h], M = B*T = 524288, N = 256, K = 128.
// 64x128 tile, two K-stages of 64 (48KB smem), 4x8 micro-tile, FFMA2.
#define BM  64
#define BN  128
#define BKK 64

__global__ void __launch_bounds__(256) gemm_cur1(const float* __restrict__ x,
                                                 const float* __restrict__ b1) {
    __shared__ float xs[BM][BKK];    // 16 KB
    __shared__ float ws[BKK][BN];    // 32 KB

    const int bm = blockIdx.x * BM;
    const int bn = blockIdx.y * BN;
    const int tid = threadIdx.x;
    const int tx = tid & 15;         // 8 output cols = 4 f32x2
    const int ty = tid >> 4;         // 4 output rows

    unsigned long long acc[4][4];
    #pragma unroll
    for (int r = 0; r < 4; r++)
        #pragma unroll
        for (int p = 0; p < 4; p++) acc[r][p] = 0ull;

    for (int k0 = 0; k0 < IN; k0 += BKK) {
        // xs: 64x64 floats = 1024 float4, 4 per thread (coalesced copy)
        #pragma unroll
        for (int l = 0; l < 4; l++) {
            int idx = tid + l * 256;
            int r = idx >> 4, c4 = idx & 15;
            *(float4*)&xs[r][c4 * 4] =
                *(const float4*)&x[(size_t)(bm + r) * IN + k0 + c4 * 4];
        }
        // ws: 64x128 floats = 2048 float4, 8 per thread (coalesced copy of w1t)
        #pragma unroll
        for (int l = 0; l < 8; l++) {
            int idx = tid + l * 256;
            int r = idx >> 5, c4 = idx & 31;
            *(float4*)&ws[r][c4 * 4] =
                *(const float4*)&g_w1t[(size_t)(k0 + r) * H + bn + c4 * 4];
        }
        __syncthreads();

        #pragma unroll 8
        for (int k = 0; k < BKK; k++) {
            ulonglong2 bq0 = *(ulonglong2*)&ws[k][tx * 8];      // cols 0..3
            ulonglong2 bq1 = *(ulonglong2*)&ws[k][tx * 8 + 4];  // cols 4..7
            #pragma unroll
            for (int r = 0; r < 4; r++) {
                unsigned long long ad;
                PACK2(ad, xs[ty * 4 + r][k]);
                FMA2(acc[r][0], ad, bq0.x);
                FMA2(acc[r][1], ad, bq0.y);
                FMA2(acc[r][2], ad, bq1.x);
                FMA2(acc[r][3], ad, bq1.y);
            }
        }
        __syncthreads();
    }

    // bias (packed) + store
    ulonglong2 bias0 = *(const ulonglong2*)&b1[bn + tx * 8];
    ulonglong2 bias1 = *(const ulonglong2*)&b1[bn + tx * 8 + 4];
    #pragma unroll
    for (int r = 0; r < 4; r++) {
        ulonglong2 o0, o1;
        ADD2(o0.x, acc[r][0], bias0.x);
        ADD2(o0.y, acc[r][1], bias0.y);
        ADD2(o1.x, acc[r][2], bias1.x);
        ADD2(o1.y, acc[r][3], bias1.y);
        float* dst = &g_cur1[(size_t)(bm + ty * 4 + r) * H + bn + tx * 8];
        *(ulonglong2*)dst       = o0;
        *(ulonglong2*)(dst + 4) = o1;
    }
}

// ---------------- phase 2: sequential scan, one CTA per batch element ---------
// 256 threads; thread t owns neuron h=t for membrane state.
// Per step: 2 barriers. Gather reads ballot words directly (ffs loop);
// slice g (64 threads) owns rows [64g, 64g+64), chunk c = float4 of columns.
// Output reduction deferred: spk2 ballots dumped to global, finalized post-loop.
__global__ void __launch_bounds__(256) scan_kernel(const float* __restrict__ b2,
                                                   const float* __restrict__ wout,
                                                   const float* __restrict__ boutp,
                                                   const float* __restrict__ pb1,
                                                   const float* __restrict__ pb2,
                                                   const float* __restrict__ pbo,
                                                   float* __restrict__ out) {
    const int b    = blockIdx.x;
    const int tid  = threadIdx.x;
    const int lane = tid & 31;
    const int wid  = tid >> 5;
    const int g    = tid >> 6;   // row-slice 0..3
    const int c    = tid & 63;   // float4 chunk 0..63

    const float bt1 = fminf(fmaxf(pb1[0], 0.f), 1.f);
    const float bt2 = fminf(fmaxf(pb2[0], 0.f), 1.f);
    const float bto = fminf(fmaxf(pbo[0], 0.f), 1.f);
    const float boutv = boutp[0];
    const float b2v   = b2[tid];

    __shared__ unsigned bits[8];
    __shared__ float    part[4][H];      // 4KB; reused as out_s[1024] post-loop
    __shared__ float    wout_sm[H];      // 1KB

    wout_sm[tid] = wout[tid];

    float mem1 = 0.f, mem2 = 0.f;
    float s1p = 0.f, s2p = 0.f;

    const float* c1p   = g_cur1 + (size_t)b * T * H + tid;
    unsigned*    spkp  = g_spk + (size_t)b * T * 8;
    float*       outp  = out + (size_t)b * T;
    const float* gbase = g_w2t + c * 4;

    // software-pipeline cur1 one step ahead
    float c1 = c1p[0];

    for (int t = 0; t < T; t++) {
        float c1n = (t + 1 < T) ? c1p[(size_t)(t + 1) * H] : 0.f;

        // layer 1 membrane update (reset uses previous-step spike)
        mem1 = bt1 * mem1 + c1 - s1p;
        bool s1 = mem1 > 1.0f;
        unsigned bal = __ballot_sync(0xffffffffu, s1);
        if (lane == 0) bits[wid] = bal;
        s1p = s1 ? 1.f : 0.f;
        __syncthreads();                          // sync1: bits ready

        // gather: rows from words 2g and 2g+1 (neurons 64g.. / 64g+32..)
        unsigned m0 = bits[2 * g], m1 = bits[2 * g + 1];
        float4 aA = make_float4(0.f, 0.f, 0.f, 0.f);
        float4 aB = make_float4(0.f, 0.f, 0.f, 0.f);
        const float* r0 = gbase + (size_t)(64 * g) * H;
        const float* r1 = gbase + (size_t)(64 * g + 32) * H;
        while (m0) {
            int j = __ffs(m0) - 1; m0 &= m0 - 1;
            float4 w = *(const float4*)(r0 + (size_t)j * H);
            aA.x += w.x; aA.y += w.y; aA.z += w.z; aA.w += w.w;
        }
        while (m1) {
            int j = __ffs(m1) - 1; m1 &= m1 - 1;
            float4 w = *(const float4*)(r1 + (size_t)j * H);
            aB.x += w.x; aB.y += w.y; aB.z += w.z; aB.w += w.w;
        }
        aA.x += aB.x; aA.y += aB.y; aA.z += aB.z; aA.w += aB.w;
        *(float4*)&part[g][c * 4] = aA;
        __syncthreads();                          // sync2: partials ready

        float cur2 = b2v + ((part[0][tid] + part[1][tid]) +
                            (part[2][tid] + part[3][tid]));

        // layer 2 membrane update
        mem2 = bt2 * mem2 + cur2 - s2p;
        bool s2 = mem2 > 1.0f;
        s2p = s2 ? 1.f : 0.f;

        // record spk2 ballot (off critical path; reduced after the loop)
        unsigned bal2 = __ballot_sync(0xffffffffu, s2);
        if (lane == 0) spkp[(size_t)t * 8 + wid] = bal2;

        c1 = c1n;
    }

    // ---------------- deferred output: out_t = bout + sum(spk2 .* wout) -------
    __syncthreads();   // global+shared writes visible block-wide
    float* out_s = &part[0][0];                   // reuse 4KB as out_s[1024]
    #pragma unroll
    for (int i = 0; i < 4; i++) {
        int t = tid + i * 256;
        float o = boutv;
        #pragma unroll
        for (int w = 0; w < 8; w++) {
            unsigned m = spkp[(size_t)t * 8 + w];
            const float* wo = wout_sm + w * 32;
            while (m) {
                int j = __ffs(m) - 1; m &= m - 1;
                o += wo[j];
            }
        }
        out_s[t] = o;
    }
    __syncthreads();
    if (tid == 0) {                               // exact serial memo recurrence
        float memo = 0.f;
        for (int t = 0; t < T; t++) {
            memo = bto * memo + out_s[t];
            out_s[t] = memo;
        }
    }
    __syncthreads();
    #pragma unroll
    for (int i = 0; i < 4; i++) {
        int t = tid + i * 256;
        outp[t] = out_s[t];
    }
}

// ---------------- launcher ----------------------------------------------------
extern "C" void kernel_launch(void* const* d_in, const int* in_sizes, int n_in,
                              void* d_out, int out_size) {
    const float* x     = (const float*)d_in[0];   // [B,T,IN]
    const float* W1    = (const float*)d_in[1];   // [H,IN]
    const float* b1    = (const float*)d_in[2];   // [H]
    const float* W2    = (const float*)d_in[3];   // [H,H]
    const float* b2    = (const float*)d_in[4];   // [H]
    const float* Wout  = (const float*)d_in[5];   // [1,H]
    const float* bout  = (const float*)d_in[6];   // [1]
    const float* beta1 = (const float*)d_in[7];
    const float* beta2 = (const float*)d_in[8];
    const float* betao = (const float*)d_in[9];
    float* out = (float*)d_out;                   // [B,T,1]

    prep_kernel<<<(H * H + 255) / 256, 256>>>(W1, W2);

    dim3 ggrid(B * T / BM, H / BN);
    gemm_cur1<<<ggrid, 256>>>(x, b1);

    scan_kernel<<<B, 256>>>(b2, Wout, bout, beta1, beta2, betao, out);
}